// round 11
// baseline (speedup 1.0000x reference)
#include <cuda_runtime.h>
#include <cuda_bf16.h>
#include <cstdint>

// ---------------------------------------------------------------------------
// Problem constants: x[16,256,64,64], Wqkv[384,256], Wout[256,128], bout[256]
// ---------------------------------------------------------------------------
#define BATCH   16
#define CDIM    256
#define NPIX    4096          // 64*64
#define HEADS   4
#define DH      32
#define INNER   128           // HEADS*DH
#define OC3     384           // 3*INNER
#define LNEPS   1e-5f
// fold (v / N) and (q / sqrt(DH)) into context
#define CTX_SCALE (0.17677669529663688f / 4096.0f)

// ---------------------------------------------------------------------------
// Scratch (static __device__ arrays; no allocations allowed)
// ---------------------------------------------------------------------------
__device__ float g_qkv [ (size_t)BATCH * OC3   * NPIX ];   // ~100 MB
__device__ float g_outh[ (size_t)BATCH * INNER * NPIX ];   // ~33 MB
__device__ float g_proj[ (size_t)BATCH * CDIM  * NPIX ];   // ~67 MB
__device__ float g_mu  [ BATCH * NPIX ];
__device__ float g_rstd[ BATCH * NPIX ];
__device__ float g_ctx [ BATCH * HEADS * DH * DH ];
__device__ float g_wsum[ OC3 ];

// ---------------------------------------------------------------------------
// Packed f32x2 FMA (sm_103a FFMA2): d = a*b + d elementwise on 2 floats
// ---------------------------------------------------------------------------
union F2U { float2 f; unsigned long long u; };

__device__ __forceinline__ void ffma2(F2U& d, const F2U& a, const F2U& b) {
    asm("fma.rn.f32x2 %0, %1, %2, %0;" : "+l"(d.u) : "l"(a.u), "l"(b.u));
}

// ---------------------------------------------------------------------------
// K0: row sums of Wqkv (for LayerNorm folding into GEMM1)
// ---------------------------------------------------------------------------
__global__ void wsum_kernel(const float* __restrict__ W) {
    int o = threadIdx.x;                 // 384 threads
    float s = 0.f;
    #pragma unroll 8
    for (int c = 0; c < CDIM; c++) s += W[o * CDIM + c];
    g_wsum[o] = s;
}

// ---------------------------------------------------------------------------
// K1: per-position channel-LN stats of x
// ---------------------------------------------------------------------------
__global__ void ln_stats_kernel(const float* __restrict__ x) {
    int p = blockIdx.x * blockDim.x + threadIdx.x;   // 0..65535
    int b = p >> 12, n = p & (NPIX - 1);
    const float* px = x + (size_t)b * CDIM * NPIX + n;
    float s = 0.f, ss = 0.f;
    #pragma unroll 8
    for (int c = 0; c < CDIM; c++) {
        float v = px[(size_t)c * NPIX];
        s += v; ss += v * v;
    }
    float mu  = s * (1.f / CDIM);
    float var = ss * (1.f / CDIM) - mu * mu;
    g_mu[p]   = mu;
    g_rstd[p] = rsqrtf(var + LNEPS);
}

// ---------------------------------------------------------------------------
// GEMM: C[b] = A[Mtot,Kdim] * Bsrc[b][Kdim,NPIX]  (128x128x16 tiles, FFMA2)
// EPI==0: Bsrc = Bin (raw x), C = g_qkv, epilogue folds the channel LN:
//         qkv = rstd[n] * (acc - mu[n] * wsum[o])
// EPI==1: Bsrc = g_outh, C = g_proj, epilogue adds bias[o]
// ---------------------------------------------------------------------------
#define BM 128
#define BN 128
#define BK 16

template<int Mtot, int Kdim, int EPI>
__global__ __launch_bounds__(256, 2)
void gemm_kernel(const float* __restrict__ A,
                 const float* __restrict__ Bin,
                 const float* __restrict__ bias)
{
    const int b  = blockIdx.z;
    const int m0 = blockIdx.y * BM;
    const int n0 = blockIdx.x * BN;

    const float* Bbase = (EPI == 0) ? Bin : (const float*)g_outh;
    const float* Bp = Bbase + (size_t)b * Kdim * NPIX;

    __shared__ __align__(16) float As[BK][BM + 4];
    __shared__ __align__(16) float Bs[BK][BN];

    const int tid  = threadIdx.x;          // 0..255
    const int tx   = tid & 15;
    const int ty   = tid >> 4;
    const int row0 = ty * 8;
    const int col0 = tx * 8;

    F2U acc[8][4];
    #pragma unroll
    for (int i = 0; i < 8; i++)
        #pragma unroll
        for (int j = 0; j < 4; j++) acc[i][j].u = 0ull;

    for (int k0 = 0; k0 < Kdim; k0 += BK) {
        // ---- A tile: rows m0..m0+127, cols k0..k0+15 -> transposed smem ----
        #pragma unroll
        for (int i = 0; i < 2; i++) {
            int f = tid * 2 + i;          // 0..511 float4s
            int r = f >> 2;               // 0..127
            int q = (f & 3) << 2;         // 0,4,8,12
            float4 v = *(const float4*)(A + (size_t)(m0 + r) * Kdim + k0 + q);
            As[q + 0][r] = v.x; As[q + 1][r] = v.y;
            As[q + 2][r] = v.z; As[q + 3][r] = v.w;
        }
        // ---- B tile: rows k0..k0+15, cols n0..n0+127 ----
        #pragma unroll
        for (int i = 0; i < 2; i++) {
            int f = i * 256 + tid;        // 0..511 float4s
            int r = f >> 5;               // 0..15
            int c = (f & 31) << 2;
            *(float4*)&Bs[r][c] = *(const float4*)(Bp + (size_t)(k0 + r) * NPIX + n0 + c);
        }
        __syncthreads();

        #pragma unroll
        for (int kk = 0; kk < BK; kk++) {
            float4 a03 = *(const float4*)&As[kk][row0];
            float4 a47 = *(const float4*)&As[kk][row0 + 4];
            float4 b03 = *(const float4*)&Bs[kk][col0];
            float4 b47 = *(const float4*)&Bs[kk][col0 + 4];
            float av[8] = {a03.x, a03.y, a03.z, a03.w, a47.x, a47.y, a47.z, a47.w};
            F2U bp[4];
            bp[0].f = make_float2(b03.x, b03.y);
            bp[1].f = make_float2(b03.z, b03.w);
            bp[2].f = make_float2(b47.x, b47.y);
            bp[3].f = make_float2(b47.z, b47.w);
            #pragma unroll
            for (int i = 0; i < 8; i++) {
                F2U ad; ad.f = make_float2(av[i], av[i]);
                #pragma unroll
                for (int j = 0; j < 4; j++) ffma2(acc[i][j], ad, bp[j]);
            }
        }
        __syncthreads();
    }

    // ---------------- epilogue ----------------
    if constexpr (EPI == 0) {
        float muv[8], rsv[8];
        int nb = b * NPIX + n0 + col0;
        #pragma unroll
        for (int j = 0; j < 8; j++) { muv[j] = g_mu[nb + j]; rsv[j] = g_rstd[nb + j]; }
        #pragma unroll
        for (int i = 0; i < 8; i++) {
            int o = m0 + row0 + i;
            float ws = g_wsum[o];
            float* dst = g_qkv + ((size_t)b * OC3 + o) * NPIX + n0 + col0;
            float vals[8];
            #pragma unroll
            for (int j = 0; j < 8; j++) {
                float a = (j & 1) ? acc[i][j >> 1].f.y : acc[i][j >> 1].f.x;
                vals[j] = rsv[j] * (a - muv[j] * ws);
            }
            *(float4*)dst       = make_float4(vals[0], vals[1], vals[2], vals[3]);
            *(float4*)(dst + 4) = make_float4(vals[4], vals[5], vals[6], vals[7]);
        }
    } else {
        #pragma unroll
        for (int i = 0; i < 8; i++) {
            int o = m0 + row0 + i;
            float bi = bias[o];
            float* dst = g_proj + ((size_t)b * CDIM + o) * NPIX + n0 + col0;
            float vals[8];
            #pragma unroll
            for (int j = 0; j < 8; j++) {
                float a = (j & 1) ? acc[i][j >> 1].f.y : acc[i][j >> 1].f.x;
                vals[j] = a + bi;
            }
            *(float4*)dst       = make_float4(vals[0], vals[1], vals[2], vals[3]);
            *(float4*)(dst + 4) = make_float4(vals[4], vals[5], vals[6], vals[7]);
        }
    }
}

// ---------------------------------------------------------------------------
// K3: k softmax over N (in-place on g_qkv channels [128,256) per batch)
// one block per (b, kchan) row of 4096 contiguous floats
// ---------------------------------------------------------------------------
__device__ __forceinline__ float warpMax(float v) {
    #pragma unroll
    for (int o = 16; o; o >>= 1) v = fmaxf(v, __shfl_xor_sync(0xffffffffu, v, o));
    return v;
}
__device__ __forceinline__ float warpSum(float v) {
    #pragma unroll
    for (int o = 16; o; o >>= 1) v += __shfl_xor_sync(0xffffffffu, v, o);
    return v;
}

__global__ void ksoftmax_kernel() {
    int rid = blockIdx.x;                        // 0..2047
    int b = rid >> 7, c = rid & 127;
    float* row = g_qkv + ((size_t)b * OC3 + INNER + c) * NPIX;
    int t = threadIdx.x;                         // 256
    __shared__ float red[8];

    float4 v[4];
    #pragma unroll
    for (int i = 0; i < 4; i++)
        v[i] = *(const float4*)(row + (size_t)(i * 256 + t) * 4);

    float m = -1e30f;
    #pragma unroll
    for (int i = 0; i < 4; i++) {
        m = fmaxf(m, fmaxf(fmaxf(v[i].x, v[i].y), fmaxf(v[i].z, v[i].w)));
    }
    m = warpMax(m);
    if ((t & 31) == 0) red[t >> 5] = m;
    __syncthreads();
    float M = red[0];
    #pragma unroll
    for (int w = 1; w < 8; w++) M = fmaxf(M, red[w]);
    __syncthreads();

    float s = 0.f;
    #pragma unroll
    for (int i = 0; i < 4; i++) {
        v[i].x = __expf(v[i].x - M); s += v[i].x;
        v[i].y = __expf(v[i].y - M); s += v[i].y;
        v[i].z = __expf(v[i].z - M); s += v[i].z;
        v[i].w = __expf(v[i].w - M); s += v[i].w;
    }
    s = warpSum(s);
    if ((t & 31) == 0) red[t >> 5] = s;
    __syncthreads();
    float S = 0.f;
    #pragma unroll
    for (int w = 0; w < 8; w++) S += red[w];
    float inv = 1.0f / S;

    #pragma unroll
    for (int i = 0; i < 4; i++) {
        v[i].x *= inv; v[i].y *= inv; v[i].z *= inv; v[i].w *= inv;
        *(float4*)(row + (size_t)(i * 256 + t) * 4) = v[i];
    }
}

// ---------------------------------------------------------------------------
// K4: context[b,h,d,e] = CTX_SCALE * sum_n ksm[d,n] * v[e,n]
// one block per (b,h); 32x32 threads, thread (e=tx, d=ty)
// ---------------------------------------------------------------------------
__global__ __launch_bounds__(1024)
void context_kernel() {
    int bh = blockIdx.x;                 // 0..63
    int b = bh >> 2, h = bh & 3;
    __shared__ float ks[DH][65];
    __shared__ float vs[DH][65];
    int tx = threadIdx.x, ty = threadIdx.y;
    int tid = ty * 32 + tx;
    int dr = tid >> 5, j2 = tid & 31;

    const float* kbase = g_qkv + ((size_t)b * OC3 + INNER     + h * DH + dr) * NPIX;
    const float* vbase = g_qkv + ((size_t)b * OC3 + 2 * INNER + h * DH + dr) * NPIX;

    float acc = 0.f;
    for (int n0 = 0; n0 < NPIX; n0 += 64) {
        float2 kv = *(const float2*)(kbase + n0 + j2 * 2);
        float2 vv = *(const float2*)(vbase + n0 + j2 * 2);
        ks[dr][j2 * 2] = kv.x; ks[dr][j2 * 2 + 1] = kv.y;
        vs[dr][j2 * 2] = vv.x; vs[dr][j2 * 2 + 1] = vv.y;
        __syncthreads();
        #pragma unroll 16
        for (int j = 0; j < 64; j++)
            acc += ks[ty][j] * vs[tx][j];
        __syncthreads();
    }
    g_ctx[(bh * DH + ty) * DH + tx] = acc * CTX_SCALE;
}

// ---------------------------------------------------------------------------
// K5: q softmax over dh + apply context:
//   outh[b, h*32+e, n] = (sum_d ctx[d,e]*exp(q[d,n]-max)) / sum_d exp(...)
// grid (NPIX/128, B*HEADS), 256 threads
// ---------------------------------------------------------------------------
__global__ void qsm_apply_kernel() {
    int bh = blockIdx.y;
    int b = bh >> 2, h = bh & 3;
    int n0 = blockIdx.x * 128;
    __shared__ __align__(16) float qs[DH][132];
    __shared__ __align__(16) float cs[DH][DH];
    __shared__ float invs[128];
    int t = threadIdx.x;                 // 256

    // load q tile [32 d][128 n] (coalesced)
    #pragma unroll
    for (int i = 0; i < 4; i++) {
        int f = i * 256 + t;             // 0..1023 float4s
        int d = f >> 5, c4 = (f & 31) << 2;
        *(float4*)&qs[d][c4] =
            *(const float4*)(g_qkv + ((size_t)b * OC3 + h * DH + d) * NPIX + n0 + c4);
    }
    // load ctx [32][32]
    #pragma unroll
    for (int i = 0; i < 4; i++)
        ((float*)cs)[i * 256 + t] = g_ctx[bh * 1024 + i * 256 + t];
    __syncthreads();

    // softmax over d per column (unnormalized; keep 1/sum)
    if (t < 128) {
        float m = -1e30f;
        #pragma unroll
        for (int d = 0; d < DH; d++) m = fmaxf(m, qs[d][t]);
        float s = 0.f;
        #pragma unroll
        for (int d = 0; d < DH; d++) {
            float e = __expf(qs[d][t] - m);
            qs[d][t] = e;
            s += e;
        }
        invs[t] = 1.0f / s;
    }
    __syncthreads();

    // apply: thread owns column nc and 16 e-rows
    int nc = t & 127;
    int eh = (t >> 7) * 16;
    float acc[16];
    #pragma unroll
    for (int i = 0; i < 16; i++) acc[i] = 0.f;
    #pragma unroll
    for (int d = 0; d < DH; d++) {
        float qv = qs[d][nc];
        #pragma unroll
        for (int e = 0; e < 16; e++)
            acc[e] += cs[d][eh + e] * qv;
    }
    float w = invs[nc];
    float* obase = g_outh + ((size_t)b * INNER + h * DH + eh) * NPIX + n0 + nc;
    #pragma unroll
    for (int e = 0; e < 16; e++)
        obase[(size_t)e * NPIX] = acc[e] * w;
}

// ---------------------------------------------------------------------------
// K7: output channel-LN of g_proj + residual x -> d_out
// ---------------------------------------------------------------------------
__global__ void out_ln_kernel(const float* __restrict__ x, float* __restrict__ out) {
    int p = blockIdx.x * blockDim.x + threadIdx.x;   // 0..65535
    int b = p >> 12, n = p & (NPIX - 1);
    size_t base = (size_t)b * CDIM * NPIX + n;
    const float* pp = g_proj + base;

    float s = 0.f, ss = 0.f;
    #pragma unroll 8
    for (int c = 0; c < CDIM; c++) {
        float v = pp[(size_t)c * NPIX];
        s += v; ss += v * v;
    }
    float mu   = s * (1.f / CDIM);
    float rstd = rsqrtf(ss * (1.f / CDIM) - mu * mu + LNEPS);

    const float* px = x + base;
    float* po = out + base;
    #pragma unroll 8
    for (int c = 0; c < CDIM; c++) {
        po[(size_t)c * NPIX] = (pp[(size_t)c * NPIX] - mu) * rstd + px[(size_t)c * NPIX];
    }
}

// ---------------------------------------------------------------------------
// launch
// ---------------------------------------------------------------------------
extern "C" void kernel_launch(void* const* d_in, const int* in_sizes, int n_in,
                              void* d_out, int out_size) {
    const float* x    = (const float*)d_in[0];   // [16,256,64,64]
    const float* Wqkv = (const float*)d_in[1];   // [384,256]
    const float* Wout = (const float*)d_in[2];   // [256,128]
    const float* bout = (const float*)d_in[3];   // [256]
    float* out = (float*)d_out;

    wsum_kernel<<<1, OC3>>>(Wqkv);
    ln_stats_kernel<<<(BATCH * NPIX) / 256, 256>>>(x);

    // GEMM1: qkv = LN-folded Wqkv @ x  -> g_qkv
    gemm_kernel<OC3, CDIM, 0><<<dim3(NPIX / BN, OC3 / BM, BATCH), 256>>>(Wqkv, x, nullptr);

    // k softmax over N (channels 128..255 of qkv, per batch)
    ksoftmax_kernel<<<BATCH * INNER, 256>>>();

    // context per (b,h)
    context_kernel<<<BATCH * HEADS, dim3(32, 32)>>>();

    // q softmax + apply -> g_outh
    qsm_apply_kernel<<<dim3(NPIX / 128, BATCH * HEADS), 256>>>();

    // GEMM2: proj = Wout @ outh + bout -> g_proj
    gemm_kernel<CDIM, INNER, 1><<<dim3(NPIX / BN, CDIM / BM, BATCH), 256>>>(Wout, nullptr, bout);

    // output LN + residual
    out_ln_kernel<<<(BATCH * NPIX) / 256, 256>>>(x, out);
}

// round 13
// speedup vs baseline: 1.0028x; 1.0028x over previous
#include <cuda_runtime.h>
#include <cuda_bf16.h>
#include <cstdint>

// ---------------------------------------------------------------------------
// Problem constants: x[16,256,64,64], Wqkv[384,256], Wout[256,128], bout[256]
// ---------------------------------------------------------------------------
#define BATCH   16
#define CDIM    256
#define NPIX    4096          // 64*64
#define HEADS   4
#define DH      32
#define INNER   128           // HEADS*DH
#define OC3     384           // 3*INNER
#define LNEPS   1e-5f
// fold (v / N) and (q / sqrt(DH)) into context
#define CTX_SCALE (0.17677669529663688f / 4096.0f)

// ---------------------------------------------------------------------------
// Scratch (static __device__ arrays; no allocations allowed)
// ---------------------------------------------------------------------------
__device__ float g_qkv [ (size_t)BATCH * OC3   * NPIX ];   // ~100 MB
__device__ float g_outh[ (size_t)BATCH * INNER * NPIX ];   // ~33 MB
__device__ float g_proj[ (size_t)BATCH * CDIM  * NPIX ];   // ~67 MB
__device__ float g_mu  [ BATCH * NPIX ];
__device__ float g_rstd[ BATCH * NPIX ];
__device__ float g_ctx [ BATCH * HEADS * DH * DH ];
__device__ float g_wsum[ OC3 ];

// ---------------------------------------------------------------------------
// Packed f32x2 FMA (sm_103a FFMA2): d = a*b + d elementwise on 2 floats
// ---------------------------------------------------------------------------
union F2U { float2 f; unsigned long long u; };

__device__ __forceinline__ void ffma2(F2U& d, const F2U& a, const F2U& b) {
    asm("fma.rn.f32x2 %0, %1, %2, %0;" : "+l"(d.u) : "l"(a.u), "l"(b.u));
}

// ---------------------------------------------------------------------------
// K0: row sums of Wqkv (for LayerNorm folding into GEMM1)
// ---------------------------------------------------------------------------
__global__ void wsum_kernel(const float* __restrict__ W) {
    int o = threadIdx.x;                 // 384 threads
    float s = 0.f;
    #pragma unroll 8
    for (int c = 0; c < CDIM; c++) s += W[o * CDIM + c];
    g_wsum[o] = s;
}

// ---------------------------------------------------------------------------
// K1: per-position channel-LN stats of x
// ---------------------------------------------------------------------------
__global__ void ln_stats_kernel(const float* __restrict__ x) {
    int p = blockIdx.x * blockDim.x + threadIdx.x;   // 0..65535
    int b = p >> 12, n = p & (NPIX - 1);
    const float* px = x + (size_t)b * CDIM * NPIX + n;
    float s = 0.f, ss = 0.f;
    #pragma unroll 8
    for (int c = 0; c < CDIM; c++) {
        float v = px[(size_t)c * NPIX];
        s += v; ss += v * v;
    }
    float mu  = s * (1.f / CDIM);
    float var = ss * (1.f / CDIM) - mu * mu;
    g_mu[p]   = mu;
    g_rstd[p] = rsqrtf(var + LNEPS);
}

// ---------------------------------------------------------------------------
// GEMM: C[b] = A[Mtot,Kdim] * Bsrc[b][Kdim,NPIX]  (128x128x16 tiles, FFMA2)
// EPI==0: Bsrc = Bin (raw x), C = g_qkv, epilogue folds the channel LN:
//         qkv = rstd[n] * (acc - mu[n] * wsum[o])
// EPI==1: Bsrc = g_outh, C = g_proj, epilogue adds bias[o]
// ---------------------------------------------------------------------------
#define BM 128
#define BN 128
#define BK 16

template<int Mtot, int Kdim, int EPI>
__global__ __launch_bounds__(256, 2)
void gemm_kernel(const float* __restrict__ A,
                 const float* __restrict__ Bin,
                 const float* __restrict__ bias)
{
    const int b  = blockIdx.z;
    const int m0 = blockIdx.y * BM;
    const int n0 = blockIdx.x * BN;

    const float* Bbase = (EPI == 0) ? Bin : (const float*)g_outh;
    const float* Bp = Bbase + (size_t)b * Kdim * NPIX;

    __shared__ __align__(16) float As[BK][BM + 4];
    __shared__ __align__(16) float Bs[BK][BN];

    const int tid  = threadIdx.x;          // 0..255
    const int tx   = tid & 15;
    const int ty   = tid >> 4;
    const int row0 = ty * 8;
    const int col0 = tx * 8;

    F2U acc[8][4];
    #pragma unroll
    for (int i = 0; i < 8; i++)
        #pragma unroll
        for (int j = 0; j < 4; j++) acc[i][j].u = 0ull;

    for (int k0 = 0; k0 < Kdim; k0 += BK) {
        // ---- A tile: rows m0..m0+127, cols k0..k0+15 -> transposed smem ----
        #pragma unroll
        for (int i = 0; i < 2; i++) {
            int f = tid * 2 + i;          // 0..511 float4s
            int r = f >> 2;               // 0..127
            int q = (f & 3) << 2;         // 0,4,8,12
            float4 v = *(const float4*)(A + (size_t)(m0 + r) * Kdim + k0 + q);
            As[q + 0][r] = v.x; As[q + 1][r] = v.y;
            As[q + 2][r] = v.z; As[q + 3][r] = v.w;
        }
        // ---- B tile: rows k0..k0+15, cols n0..n0+127 ----
        #pragma unroll
        for (int i = 0; i < 2; i++) {
            int f = i * 256 + tid;        // 0..511 float4s
            int r = f >> 5;               // 0..15
            int c = (f & 31) << 2;
            *(float4*)&Bs[r][c] = *(const float4*)(Bp + (size_t)(k0 + r) * NPIX + n0 + c);
        }
        __syncthreads();

        #pragma unroll
        for (int kk = 0; kk < BK; kk++) {
            float4 a03 = *(const float4*)&As[kk][row0];
            float4 a47 = *(const float4*)&As[kk][row0 + 4];
            float4 b03 = *(const float4*)&Bs[kk][col0];
            float4 b47 = *(const float4*)&Bs[kk][col0 + 4];
            float av[8] = {a03.x, a03.y, a03.z, a03.w, a47.x, a47.y, a47.z, a47.w};
            F2U bp[4];
            bp[0].f = make_float2(b03.x, b03.y);
            bp[1].f = make_float2(b03.z, b03.w);
            bp[2].f = make_float2(b47.x, b47.y);
            bp[3].f = make_float2(b47.z, b47.w);
            #pragma unroll
            for (int i = 0; i < 8; i++) {
                F2U ad; ad.f = make_float2(av[i], av[i]);
                #pragma unroll
                for (int j = 0; j < 4; j++) ffma2(acc[i][j], ad, bp[j]);
            }
        }
        __syncthreads();
    }

    // ---------------- epilogue ----------------
    if constexpr (EPI == 0) {
        float muv[8], rsv[8];
        int nb = b * NPIX + n0 + col0;
        #pragma unroll
        for (int j = 0; j < 8; j++) { muv[j] = g_mu[nb + j]; rsv[j] = g_rstd[nb + j]; }
        #pragma unroll
        for (int i = 0; i < 8; i++) {
            int o = m0 + row0 + i;
            float ws = g_wsum[o];
            float* dst = g_qkv + ((size_t)b * OC3 + o) * NPIX + n0 + col0;
            float vals[8];
            #pragma unroll
            for (int j = 0; j < 8; j++) {
                float a = (j & 1) ? acc[i][j >> 1].f.y : acc[i][j >> 1].f.x;
                vals[j] = rsv[j] * (a - muv[j] * ws);
            }
            *(float4*)dst       = make_float4(vals[0], vals[1], vals[2], vals[3]);
            *(float4*)(dst + 4) = make_float4(vals[4], vals[5], vals[6], vals[7]);
        }
    } else {
        #pragma unroll
        for (int i = 0; i < 8; i++) {
            int o = m0 + row0 + i;
            float bi = bias[o];
            float* dst = g_proj + ((size_t)b * CDIM + o) * NPIX + n0 + col0;
            float vals[8];
            #pragma unroll
            for (int j = 0; j < 8; j++) {
                float a = (j & 1) ? acc[i][j >> 1].f.y : acc[i][j >> 1].f.x;
                vals[j] = a + bi;
            }
            *(float4*)dst       = make_float4(vals[0], vals[1], vals[2], vals[3]);
            *(float4*)(dst + 4) = make_float4(vals[4], vals[5], vals[6], vals[7]);
        }
    }
}

// ---------------------------------------------------------------------------
// K3: k softmax over N (in-place on g_qkv channels [128,256) per batch)
// one block per (b, kchan) row of 4096 contiguous floats
// ---------------------------------------------------------------------------
__device__ __forceinline__ float warpMax(float v) {
    #pragma unroll
    for (int o = 16; o; o >>= 1) v = fmaxf(v, __shfl_xor_sync(0xffffffffu, v, o));
    return v;
}
__device__ __forceinline__ float warpSum(float v) {
    #pragma unroll
    for (int o = 16; o; o >>= 1) v += __shfl_xor_sync(0xffffffffu, v, o);
    return v;
}

__global__ void ksoftmax_kernel() {
    int rid = blockIdx.x;                        // 0..2047
    int b = rid >> 7, c = rid & 127;
    float* row = g_qkv + ((size_t)b * OC3 + INNER + c) * NPIX;
    int t = threadIdx.x;                         // 256
    __shared__ float red[8];

    float4 v[4];
    #pragma unroll
    for (int i = 0; i < 4; i++)
        v[i] = *(const float4*)(row + (size_t)(i * 256 + t) * 4);

    float m = -1e30f;
    #pragma unroll
    for (int i = 0; i < 4; i++) {
        m = fmaxf(m, fmaxf(fmaxf(v[i].x, v[i].y), fmaxf(v[i].z, v[i].w)));
    }
    m = warpMax(m);
    if ((t & 31) == 0) red[t >> 5] = m;
    __syncthreads();
    float M = red[0];
    #pragma unroll
    for (int w = 1; w < 8; w++) M = fmaxf(M, red[w]);
    __syncthreads();

    float s = 0.f;
    #pragma unroll
    for (int i = 0; i < 4; i++) {
        v[i].x = __expf(v[i].x - M); s += v[i].x;
        v[i].y = __expf(v[i].y - M); s += v[i].y;
        v[i].z = __expf(v[i].z - M); s += v[i].z;
        v[i].w = __expf(v[i].w - M); s += v[i].w;
    }
    s = warpSum(s);
    if ((t & 31) == 0) red[t >> 5] = s;
    __syncthreads();
    float S = 0.f;
    #pragma unroll
    for (int w = 0; w < 8; w++) S += red[w];
    float inv = 1.0f / S;

    #pragma unroll
    for (int i = 0; i < 4; i++) {
        v[i].x *= inv; v[i].y *= inv; v[i].z *= inv; v[i].w *= inv;
        *(float4*)(row + (size_t)(i * 256 + t) * 4) = v[i];
    }
}

// ---------------------------------------------------------------------------
// K4: context[b,h,d,e] = CTX_SCALE * sum_n ksm[d,n] * v[e,n]
// one block per (b,h); 32x32 threads, thread (e=tx, d=ty)
// ---------------------------------------------------------------------------
__global__ __launch_bounds__(1024)
void context_kernel() {
    int bh = blockIdx.x;                 // 0..63
    int b = bh >> 2, h = bh & 3;
    __shared__ float ks[DH][65];
    __shared__ float vs[DH][65];
    int tx = threadIdx.x, ty = threadIdx.y;
    int tid = ty * 32 + tx;
    int dr = tid >> 5, j2 = tid & 31;

    const float* kbase = g_qkv + ((size_t)b * OC3 + INNER     + h * DH + dr) * NPIX;
    const float* vbase = g_qkv + ((size_t)b * OC3 + 2 * INNER + h * DH + dr) * NPIX;

    float acc = 0.f;
    for (int n0 = 0; n0 < NPIX; n0 += 64) {
        float2 kv = *(const float2*)(kbase + n0 + j2 * 2);
        float2 vv = *(const float2*)(vbase + n0 + j2 * 2);
        ks[dr][j2 * 2] = kv.x; ks[dr][j2 * 2 + 1] = kv.y;
        vs[dr][j2 * 2] = vv.x; vs[dr][j2 * 2 + 1] = vv.y;
        __syncthreads();
        #pragma unroll 16
        for (int j = 0; j < 64; j++)
            acc += ks[ty][j] * vs[tx][j];
        __syncthreads();
    }
    g_ctx[(bh * DH + ty) * DH + tx] = acc * CTX_SCALE;
}

// ---------------------------------------------------------------------------
// K5: q softmax over dh + apply context:
//   outh[b, h*32+e, n] = (sum_d ctx[d,e]*exp(q[d,n]-max)) / sum_d exp(...)
// grid (NPIX/128, B*HEADS), 256 threads
// ---------------------------------------------------------------------------
__global__ void qsm_apply_kernel() {
    int bh = blockIdx.y;
    int b = bh >> 2, h = bh & 3;
    int n0 = blockIdx.x * 128;
    __shared__ __align__(16) float qs[DH][132];
    __shared__ __align__(16) float cs[DH][DH];
    __shared__ float invs[128];
    int t = threadIdx.x;                 // 256

    // load q tile [32 d][128 n] (coalesced)
    #pragma unroll
    for (int i = 0; i < 4; i++) {
        int f = i * 256 + t;             // 0..1023 float4s
        int d = f >> 5, c4 = (f & 31) << 2;
        *(float4*)&qs[d][c4] =
            *(const float4*)(g_qkv + ((size_t)b * OC3 + h * DH + d) * NPIX + n0 + c4);
    }
    // load ctx [32][32]
    #pragma unroll
    for (int i = 0; i < 4; i++)
        ((float*)cs)[i * 256 + t] = g_ctx[bh * 1024 + i * 256 + t];
    __syncthreads();

    // softmax over d per column (unnormalized; keep 1/sum)
    if (t < 128) {
        float m = -1e30f;
        #pragma unroll
        for (int d = 0; d < DH; d++) m = fmaxf(m, qs[d][t]);
        float s = 0.f;
        #pragma unroll
        for (int d = 0; d < DH; d++) {
            float e = __expf(qs[d][t] - m);
            qs[d][t] = e;
            s += e;
        }
        invs[t] = 1.0f / s;
    }
    __syncthreads();

    // apply: thread owns column nc and 16 e-rows
    int nc = t & 127;
    int eh = (t >> 7) * 16;
    float acc[16];
    #pragma unroll
    for (int i = 0; i < 16; i++) acc[i] = 0.f;
    #pragma unroll
    for (int d = 0; d < DH; d++) {
        float qv = qs[d][nc];
        #pragma unroll
        for (int e = 0; e < 16; e++)
            acc[e] += cs[d][eh + e] * qv;
    }
    float w = invs[nc];
    float* obase = g_outh + ((size_t)b * INNER + h * DH + eh) * NPIX + n0 + nc;
    #pragma unroll
    for (int e = 0; e < 16; e++)
        obase[(size_t)e * NPIX] = acc[e] * w;
}

// ---------------------------------------------------------------------------
// K7: output channel-LN of g_proj + residual x -> d_out
// ---------------------------------------------------------------------------
__global__ void out_ln_kernel(const float* __restrict__ x, float* __restrict__ out) {
    int p = blockIdx.x * blockDim.x + threadIdx.x;   // 0..65535
    int b = p >> 12, n = p & (NPIX - 1);
    size_t base = (size_t)b * CDIM * NPIX + n;
    const float* pp = g_proj + base;

    float s = 0.f, ss = 0.f;
    #pragma unroll 8
    for (int c = 0; c < CDIM; c++) {
        float v = pp[(size_t)c * NPIX];
        s += v; ss += v * v;
    }
    float mu   = s * (1.f / CDIM);
    float rstd = rsqrtf(ss * (1.f / CDIM) - mu * mu + LNEPS);

    const float* px = x + base;
    float* po = out + base;
    #pragma unroll 8
    for (int c = 0; c < CDIM; c++) {
        po[(size_t)c * NPIX] = (pp[(size_t)c * NPIX] - mu) * rstd + px[(size_t)c * NPIX];
    }
}

// ---------------------------------------------------------------------------
// launch
// ---------------------------------------------------------------------------
extern "C" void kernel_launch(void* const* d_in, const int* in_sizes, int n_in,
                              void* d_out, int out_size) {
    const float* x    = (const float*)d_in[0];   // [16,256,64,64]
    const float* Wqkv = (const float*)d_in[1];   // [384,256]
    const float* Wout = (const float*)d_in[2];   // [256,128]
    const float* bout = (const float*)d_in[3];   // [256]
    float* out = (float*)d_out;

    wsum_kernel<<<1, OC3>>>(Wqkv);
    ln_stats_kernel<<<(BATCH * NPIX) / 256, 256>>>(x);

    // GEMM1: qkv = LN-folded Wqkv @ x  -> g_qkv
    gemm_kernel<OC3, CDIM, 0><<<dim3(NPIX / BN, OC3 / BM, BATCH), 256>>>(Wqkv, x, nullptr);

    // k softmax over N (channels 128..255 of qkv, per batch)
    ksoftmax_kernel<<<BATCH * INNER, 256>>>();

    // context per (b,h)
    context_kernel<<<BATCH * HEADS, dim3(32, 32)>>>();

    // q softmax + apply -> g_outh
    qsm_apply_kernel<<<dim3(NPIX / 128, BATCH * HEADS), 256>>>();

    // GEMM2: proj = Wout @ outh + bout -> g_proj
    gemm_kernel<CDIM, INNER, 1><<<dim3(NPIX / BN, CDIM / BM, BATCH), 256>>>(Wout, nullptr, bout);

    // output LN + residual
    out_ln_kernel<<<(BATCH * NPIX) / 256, 256>>>(x, out);
}